// round 16
// baseline (speedup 1.0000x reference)
#include <cuda_runtime.h>
#include <cuda_fp16.h>
#include <math.h>
#include <stdint.h>

#define BB  128
#define EMB 512
#define HH  1024
#define H3  3072
#define VV  8192
#define TT  100

#define LO_SCALE   2048.0f
#define LO_INV     (1.0f / 2048.0f)

#define NSPLIT  3
#define LSTRIDE (BB * VV)
#define GSTRIDE (BB * H3)

#define NCTA    148
#define NTILES  88            // 24 gh + 64 logits
#define UTOT    (NTILES * 32) // 2816 kt-units
#define UGH     (24 * 32)     // 768 gh-only kt-units

// ======================= device scratch (no allocs allowed) ==================
__device__ float g_h[BB * HH];
__device__ int   g_idx[BB];
__device__ float g_eproj[(size_t)VV * H3];
__device__ float g_gh_p[NSPLIT * BB * H3];
__device__ float g_logits_p[NSPLIT * BB * VV];

__device__ __align__(128) __half g_h_hi[BB * HH];
__device__ __align__(128) __half g_h_lo[BB * HH];
__device__ __align__(128) __half g_emb_hi[(size_t)VV * EMB];
__device__ __align__(128) __half g_emb_lo[(size_t)VV * EMB];
__device__ __align__(128) __half g_wih_hi[(size_t)H3 * EMB];
__device__ __align__(128) __half g_wih_lo[(size_t)H3 * EMB];
__device__ __align__(128) __half g_whh_hi[(size_t)H3 * HH];
__device__ __align__(128) __half g_whh_lo[(size_t)H3 * HH];
__device__ __align__(128) __half g_cls_hi[(size_t)VV * HH];
__device__ __align__(128) __half g_cls_lo[(size_t)VV * HH];

// ======================= helpers ============================================
__device__ __forceinline__ uint32_t smem_u32(const void* p) {
    uint32_t a;
    asm("{ .reg .u64 t; cvta.to.shared.u64 t, %1; cvt.u32.u64 %0, t; }"
        : "=r"(a) : "l"(p));
    return a;
}
__device__ __forceinline__ void cpasync16(uint32_t dst, const void* src) {
    asm volatile("cp.async.cg.shared.global [%0], [%1], 16;"
                 :: "r"(dst), "l"(src) : "memory");
}
#define CP_COMMIT() asm volatile("cp.async.commit_group;" ::: "memory")

// fp32-accumulate HMMA (main term)
__device__ __forceinline__ void mma16(float c[4], const uint32_t a[4], const uint32_t b[2]) {
    asm volatile(
        "mma.sync.aligned.m16n8k16.row.col.f32.f16.f16.f32 "
        "{%0,%1,%2,%3}, {%4,%5,%6,%7}, {%8,%9}, {%0,%1,%2,%3};"
        : "+f"(c[0]), "+f"(c[1]), "+f"(c[2]), "+f"(c[3])
        : "r"(a[0]), "r"(a[1]), "r"(a[2]), "r"(a[3]), "r"(b[0]), "r"(b[1]));
}

// fp16-accumulate HMMA (correction terms; flushed to fp32 every kt)
__device__ __forceinline__ void mma16h(uint32_t c[2], const uint32_t a[4], const uint32_t b[2]) {
    asm volatile(
        "mma.sync.aligned.m16n8k16.row.col.f16.f16.f16.f16 "
        "{%0,%1}, {%2,%3,%4,%5}, {%6,%7}, {%0,%1};"
        : "+r"(c[0]), "+r"(c[1])
        : "r"(a[0]), "r"(a[1]), "r"(a[2]), "r"(a[3]), "r"(b[0]), "r"(b[1]));
}

#define LDSM_X4(r0, r1, r2, r3, addr) \
    asm volatile("ldmatrix.sync.aligned.m8n8.x4.shared.b16 {%0,%1,%2,%3}, [%4];" \
                 : "=r"(r0), "=r"(r1), "=r"(r2), "=r"(r3) : "r"(addr))

#define SROW        40
#define PLANE_H     (128 * SROW)
#define PLANE_B     (PLANE_H * 2)
#define STAGE_H     (4 * PLANE_H)
#define STAGE_B     (4 * PLANE_B)         // 40960
#define NSTAGE      4
#define GEMM_SMEM_B (NSTAGE * STAGE_B)    // 163840

// owner CTA of global kt-unit u under the (UTOT, NCTA) contiguous partition
__device__ __forceinline__ int unit_owner(int u) {
    return (u * NCTA + NCTA - 1) / UTOT;
}

// flush fp16 correction accumulators into fp32 main accumulators (x 2^-11)
__device__ __forceinline__ void flush_clh(float cm[4], uint32_t clh[2]) {
    __half2 p0 = *(__half2*)&clh[0];
    __half2 p1 = *(__half2*)&clh[1];
    cm[0] += __half2float(__low2half(p0))  * LO_INV;
    cm[1] += __half2float(__high2half(p0)) * LO_INV;
    cm[2] += __half2float(__low2half(p1))  * LO_INV;
    cm[3] += __half2float(__high2half(p1)) * LO_INV;
    clh[0] = 0u; clh[1] = 0u;
}

// ======================= balanced step GEMM (512 thr, 4m x 4n warps) =========
// R15 core; correction MMAs use fp16 accumulators flushed per kt.
__global__ __launch_bounds__(512, 1)
void k_gemm_bal(int uMax)
{
    extern __shared__ __half smh[];
    const uint32_t sb = smem_u32(smh);

    const int cta  = blockIdx.x;
    const int tid  = threadIdx.x;
    const int wid  = tid >> 5, lane = tid & 31;
    const int grp  = lane >> 2, tig = lane & 3;
    const int wm   = wid & 3, wn = wid >> 2;     // 4 m-warps x 4 n-warps
    const int mo   = wm * 32, no = wn * 32;

    const int rc = tid >> 2, kp = tid & 3;       // gmem->smem chunk coords

    const uint32_t offA = (uint32_t)((mo + (lane & 7) + ((lane >> 3) & 1) * 8) * SROW
                                     + (lane >> 4) * 8) * 2;
    const uint32_t offB = (uint32_t)((no + (lane & 7) + (lane >> 4) * 8) * SROW
                                     + ((lane >> 3) & 1) * 8) * 2;

    int u  = (cta * UTOT) / NCTA;
    int u1 = ((cta + 1) * UTOT) / NCTA;
    if (u1 > uMax) u1 = uMax;

    while (u < u1) {
        const int tile = u >> 5;
        const int ktl0 = u & 31;
        int nkt = 32 - ktl0;
        if (nkt > u1 - u) nkt = u1 - u;
        const int slot = cta - unit_owner(tile << 5);

        // target decode
        const __half *Bhi, *Blo; float* C; int N; int n0;
        if (tile < 24) {
            Bhi = g_whh_hi; Blo = g_whh_lo;
            C = g_gh_p + (size_t)slot * GSTRIDE; N = H3; n0 = tile << 7;
        } else {
            Bhi = g_cls_hi; Blo = g_cls_lo;
            C = g_logits_p + (size_t)slot * LSTRIDE; N = VV; n0 = (tile - 24) << 7;
        }
        const int K = HH;

        const __half* gp[4];
        gp[0] = g_h_hi + (ktl0 << 5);
        gp[1] = g_h_lo + (ktl0 << 5);
        gp[2] = Bhi + (size_t)n0 * K + (ktl0 << 5);
        gp[3] = Blo + (size_t)n0 * K + (ktl0 << 5);

        float    cm[2][4][4];
        uint32_t clh[2][4][2];
#pragma unroll
        for (int mb = 0; mb < 2; mb++)
#pragma unroll
            for (int j = 0; j < 4; j++) {
#pragma unroll
                for (int i = 0; i < 4; i++) cm[mb][j][i] = 0.0f;
                clh[mb][j][0] = 0u; clh[mb][j][1] = 0u;
            }

        auto load_stage = [&](int kt, int st) {
            const int koff = kt << 5;
            const uint32_t base = sb + st * STAGE_B;
#pragma unroll
            for (int p = 0; p < 4; p++)
                cpasync16(base + p * PLANE_B + rc * (SROW * 2) + kp * 16,
                          gp[p] + (size_t)rc * K + koff + kp * 8);
            CP_COMMIT();
        };

        __syncthreads();   // prior segment's smem reads done before refill
        load_stage(0, 0);
        if (nkt > 1) load_stage(1, 1);
        if (nkt > 2) load_stage(2, 2);

        for (int kt = 0; kt < nkt; kt++) {
            const int rem = nkt - 1 - kt;
            if (rem >= 2)      asm volatile("cp.async.wait_group 2;" ::: "memory");
            else if (rem == 1) asm volatile("cp.async.wait_group 1;" ::: "memory");
            else               asm volatile("cp.async.wait_group 0;" ::: "memory");
            __syncthreads();
            if (kt + 3 < nkt) load_stage(kt + 3, (kt + 3) & (NSTAGE - 1));

            const uint32_t stb = sb + (kt & (NSTAGE - 1)) * STAGE_B;
            const uint32_t aHi = stb + offA;
            const uint32_t aLo = aHi + PLANE_B;
            const uint32_t bHi = stb + 2 * PLANE_B + offB;
            const uint32_t bLo = bHi + PLANE_B;

#pragma unroll
            for (int ks = 0; ks < 2; ks++) {
                const uint32_t kso = ks * 32;
                uint32_t ah[2][4], al[2][4];
#pragma unroll
                for (int mb = 0; mb < 2; mb++) {
                    const uint32_t amb = mb * (16 * SROW * 2) + kso;
                    LDSM_X4(ah[mb][0], ah[mb][1], ah[mb][2], ah[mb][3], aHi + amb);
                    LDSM_X4(al[mb][0], al[mb][1], al[mb][2], al[mb][3], aLo + amb);
                }
                uint32_t bh[4][2], bl[4][2];
#pragma unroll
                for (int jj = 0; jj < 4; jj += 2) {
                    const uint32_t bj = jj * (8 * SROW * 2) + kso;
                    LDSM_X4(bh[jj][0], bh[jj][1], bh[jj+1][0], bh[jj+1][1], bHi + bj);
                    LDSM_X4(bl[jj][0], bl[jj][1], bl[jj+1][0], bl[jj+1][1], bLo + bj);
                }
#pragma unroll
                for (int j = 0; j < 4; j++)
#pragma unroll
                    for (int mb = 0; mb < 2; mb++)
                        mma16(cm[mb][j], ah[mb], bh[j]);
#pragma unroll
                for (int j = 0; j < 4; j++)
#pragma unroll
                    for (int mb = 0; mb < 2; mb++)
                        mma16h(clh[mb][j], ah[mb], bl[j]);
#pragma unroll
                for (int j = 0; j < 4; j++)
#pragma unroll
                    for (int mb = 0; mb < 2; mb++)
                        mma16h(clh[mb][j], al[mb], bh[j]);
            }
            // flush fp16 corrections into fp32 accumulators (K=32 window)
#pragma unroll
            for (int mb = 0; mb < 2; mb++)
#pragma unroll
                for (int j = 0; j < 4; j++)
                    flush_clh(cm[mb][j], clh[mb][j]);
        }

        // epilogue: C_slot = cm (corrections already folded)
#pragma unroll
        for (int mb = 0; mb < 2; mb++) {
#pragma unroll
            for (int j = 0; j < 4; j++) {
                const int col = n0 + no + j * 8 + 2 * tig;
                const int r0 = mo + mb * 16 + grp;
                const int r1 = r0 + 8;
                float2 v0, v1;
                v0.x = cm[mb][j][0];
                v0.y = cm[mb][j][1];
                v1.x = cm[mb][j][2];
                v1.y = cm[mb][j][3];
                *(float2*)(C + (size_t)r0 * N + col) = v0;
                *(float2*)(C + (size_t)r1 * N + col) = v1;
            }
        }

        u += nkt;
    }
}

// ======================= generic GEMM (eproj prologue only) ==================
__global__ __launch_bounds__(512, 1)
void k_gemm_h(const __half* __restrict__ Ahi, const __half* __restrict__ Alo,
              const __half* __restrict__ Bhi, const __half* __restrict__ Blo,
              float* __restrict__ C, int N, int K)
{
    extern __shared__ __half smh[];
    const uint32_t sb = smem_u32(smh);

    const int tid  = threadIdx.x;
    const int wid  = tid >> 5, lane = tid & 31;
    const int grp  = lane >> 2, tig = lane & 3;
    const int wm   = wid & 3, wn = wid >> 2;
    const int mo   = wm * 32, no = wn * 32;

    const int ntn = N >> 7;
    const int tn = blockIdx.x % ntn, tm = blockIdx.x / ntn;
    const int m0 = tm << 7, n0 = tn << 7;
    const int nk = K >> 5;

    const __half* gp[4];
    gp[0] = Ahi + (size_t)m0 * K;
    gp[1] = Alo + (size_t)m0 * K;
    gp[2] = Bhi + (size_t)n0 * K;
    gp[3] = Blo + (size_t)n0 * K;

    const int rc = tid >> 2, kp = tid & 3;

    const uint32_t offA = (uint32_t)((mo + (lane & 7) + ((lane >> 3) & 1) * 8) * SROW
                                     + (lane >> 4) * 8) * 2;
    const uint32_t offB = (uint32_t)((no + (lane & 7) + (lane >> 4) * 8) * SROW
                                     + ((lane >> 3) & 1) * 8) * 2;

    float    cm[2][4][4];
    uint32_t clh[2][4][2];
#pragma unroll
    for (int mb = 0; mb < 2; mb++)
#pragma unroll
        for (int j = 0; j < 4; j++) {
#pragma unroll
            for (int i = 0; i < 4; i++) cm[mb][j][i] = 0.0f;
            clh[mb][j][0] = 0u; clh[mb][j][1] = 0u;
        }

    auto load_stage = [&](int kt, int st) {
        const int koff = kt << 5;
        const uint32_t base = sb + st * STAGE_B;
#pragma unroll
        for (int p = 0; p < 4; p++)
            cpasync16(base + p * PLANE_B + rc * (SROW * 2) + kp * 16,
                      gp[p] + (size_t)rc * K + koff + kp * 8);
        CP_COMMIT();
    };

    load_stage(0, 0);
    load_stage(1, 1);

    for (int kt = 0; kt < nk; kt++) {
        if (kt + 1 < nk) asm volatile("cp.async.wait_group 1;" ::: "memory");
        else             asm volatile("cp.async.wait_group 0;" ::: "memory");
        __syncthreads();
        if (kt + 2 < nk) load_stage(kt + 2, (kt + 2) & (NSTAGE - 1));

        const uint32_t stb = sb + (kt & (NSTAGE - 1)) * STAGE_B;
        const uint32_t aHi = stb + offA;
        const uint32_t aLo = aHi + PLANE_B;
        const uint32_t bHi = stb + 2 * PLANE_B + offB;
        const uint32_t bLo = bHi + PLANE_B;

#pragma unroll
        for (int ks = 0; ks < 2; ks++) {
            const uint32_t kso = ks * 32;
            uint32_t ah[2][4], al[2][4];
#pragma unroll
            for (int mb = 0; mb < 2; mb++) {
                const uint32_t amb = mb * (16 * SROW * 2) + kso;
                LDSM_X4(ah[mb][0], ah[mb][1], ah[mb][2], ah[mb][3], aHi + amb);
                LDSM_X4(al[mb][0], al[mb][1], al[mb][2], al[mb][3], aLo + amb);
            }
            uint32_t bh[4][2], bl[4][2];
#pragma unroll
            for (int jj = 0; jj < 4; jj += 2) {
                const uint32_t bj = jj * (8 * SROW * 2) + kso;
                LDSM_X4(bh[jj][0], bh[jj][1], bh[jj+1][0], bh[jj+1][1], bHi + bj);
                LDSM_X4(bl[jj][0], bl[jj][1], bl[jj+1][0], bl[jj+1][1], bLo + bj);
            }
#pragma unroll
            for (int j = 0; j < 4; j++)
#pragma unroll
                for (int mb = 0; mb < 2; mb++)
                    mma16(cm[mb][j], ah[mb], bh[j]);
#pragma unroll
            for (int j = 0; j < 4; j++)
#pragma unroll
                for (int mb = 0; mb < 2; mb++)
                    mma16h(clh[mb][j], ah[mb], bl[j]);
#pragma unroll
            for (int j = 0; j < 4; j++)
#pragma unroll
                for (int mb = 0; mb < 2; mb++)
                    mma16h(clh[mb][j], al[mb], bh[j]);
        }
#pragma unroll
        for (int mb = 0; mb < 2; mb++)
#pragma unroll
            for (int j = 0; j < 4; j++)
                flush_clh(cm[mb][j], clh[mb][j]);
    }

#pragma unroll
    for (int mb = 0; mb < 2; mb++) {
#pragma unroll
        for (int j = 0; j < 4; j++) {
            const int col = n0 + no + j * 8 + 2 * tig;
            const int r0 = m0 + mo + mb * 16 + grp;
            const int r1 = r0 + 8;
            float2 v0, v1;
            v0.x = cm[mb][j][0];
            v0.y = cm[mb][j][1];
            v1.x = cm[mb][j][2];
            v1.y = cm[mb][j][3];
            *(float2*)(C + (size_t)r0 * N + col) = v0;
            *(float2*)(C + (size_t)r1 * N + col) = v1;
        }
    }
}

// ======================= small kernels ======================================
__device__ __forceinline__ void split_h(float a, __half* hi, __half* lo) {
    __half h = __float2half_rn(a);
    float r = a - __half2float(h);
    *hi = h;
    *lo = __float2half_rn(r * LO_SCALE);
}

__device__ __forceinline__ void split4(const float* src, __half* hi, __half* lo,
                                       int j) {
    float4 v = *(const float4*)(src + j);
    __half h0, h1, h2, h3, l0, l1, l2, l3;
    split_h(v.x, &h0, &l0); split_h(v.y, &h1, &l1);
    split_h(v.z, &h2, &l2); split_h(v.w, &h3, &l3);
    *(__half2*)(hi + j)     = __halves2half2(h0, h1);
    *(__half2*)(hi + j + 2) = __halves2half2(h2, h3);
    *(__half2*)(lo + j)     = __halves2half2(l0, l1);
    *(__half2*)(lo + j + 2) = __halves2half2(l2, l3);
}

#define N_EMB (VV * EMB)
#define N_WIH (H3 * EMB)
#define N_WHH (H3 * HH)
#define N_CLS (VV * HH)
#define N_ALL (N_EMB + N_WIH + N_WHH + N_CLS)

__global__ void k_split_all(const float* __restrict__ emb,
                            const float* __restrict__ w_ih,
                            const float* __restrict__ w_hh,
                            const float* __restrict__ cls_w)
{
    int i = (blockIdx.x * blockDim.x + threadIdx.x) * 4;
    if (i >= N_ALL) return;
    if (i < N_EMB) {
        split4(emb, g_emb_hi, g_emb_lo, i);
    } else if (i < N_EMB + N_WIH) {
        split4(w_ih, g_wih_hi, g_wih_lo, i - N_EMB);
    } else if (i < N_EMB + N_WIH + N_WHH) {
        split4(w_hh, g_whh_hi, g_whh_lo, i - N_EMB - N_WIH);
    } else {
        split4(cls_w, g_cls_hi, g_cls_lo, i - N_EMB - N_WIH - N_WHH);
    }
}

__global__ void k_init(const float* __restrict__ x, float* __restrict__ out)
{
    int i = blockIdx.x * blockDim.x + threadIdx.x;      // grid covers BB*VV
    float L = logf(expf(1.0f) + (float)(VV - 1));
    if (i < BB * VV) {
        int b = i / VV, v = i % VV;
        out[(size_t)b * TT * VV + v] = (v == 0 ? 1.0f : 0.0f) - L;
        // zero all partial slots (statically-unwritten ones must read as 0)
#pragma unroll
        for (int j = 0; j < NSPLIT; j++) g_logits_p[i + j * LSTRIDE] = 0.0f;
        if (i < NSPLIT * BB * H3 - BB * VV)
            g_gh_p[BB * VV + i] = 0.0f;
        if (i < BB * VV) {
            if (i < NSPLIT * BB * H3 && i < BB * VV) g_gh_p[i] = 0.0f;
        }
    }
    if (i < BB * HH) {
        float h = x[i];
        g_h[i] = h;
        split_h(h, g_h_hi + i, g_h_lo + i);
    }
    if (i < BB) g_idx[i] = 0;
}

// ======================= fused softmax + argmax + GRU gates ==================
__global__ __launch_bounds__(1024)
void k_post(float* __restrict__ out, int t, int doSoftmax,
            const float* __restrict__ cls_b,
            const float* __restrict__ b_ih,
            const float* __restrict__ b_hh)
{
    const int b = blockIdx.x;
    const int tid = threadIdx.x;

    __shared__ float s_v[1024];
    __shared__ int   s_i[1024];

    int gidx;
    if (doSoftmax) {
        const float* lp = g_logits_p + (size_t)b * VV;
        float* orow = out + ((size_t)b * TT + t) * VV;

        float x[8];
        float mx = -__int_as_float(0x7f800000);
        int   ai = 0;
#pragma unroll
        for (int j = 0; j < 8; j++) {
            int idx = tid + j * 1024;
            x[j] = lp[idx] + lp[idx + LSTRIDE] + lp[idx + 2 * LSTRIDE] + cls_b[idx];
            if (x[j] > mx) { mx = x[j]; ai = idx; }
        }
        s_v[tid] = mx; s_i[tid] = ai;
        __syncthreads();
#pragma unroll
        for (int s = 512; s > 0; s >>= 1) {
            if (tid < s) {
                float v2 = s_v[tid + s]; int i2 = s_i[tid + s];
                if (v2 > s_v[tid] || (v2 == s_v[tid] && i2 < s_i[tid])) {
                    s_v[tid] = v2; s_i[tid] = i2;
                }
            }
            __syncthreads();
        }
        float gmax = s_v[0];
        gidx = s_i[0];
        __syncthreads();

        float sum = 0.0f;
#pragma unroll
        for (int j = 0; j < 8; j++) sum += __expf(x[j] - gmax);
        s_v[tid] = sum;
        __syncthreads();
#pragma unroll
        for (int s = 512; s > 0; s >>= 1) {
            if (tid < s) s_v[tid] += s_v[tid + s];
            __syncthreads();
        }
        float lse = gmax + logf(s_v[0]);

#pragma unroll
        for (int j = 0; j < 8; j++)
            orow[tid + j * 1024] = x[j] - lse;

        if (tid == 0) g_idx[b] = gidx;
    } else {
        gidx = g_idx[b];
    }

    // ---- GRU gates for h[b, tid] ----
    {
        const int i = tid;
        const int g = b * HH + i;
        const float* ep = g_eproj + (size_t)gidx * H3;
        const float* gp = g_gh_p + (size_t)b * H3;

        float gi_r = ep[i]          + b_ih[i];
        float gi_z = ep[HH + i]     + b_ih[HH + i];
        float gi_n = ep[2 * HH + i] + b_ih[2 * HH + i];

        float gh_r = gp[i] + gp[i + GSTRIDE] + gp[i + 2 * GSTRIDE] + b_hh[i];
        float gh_z = gp[HH + i] + gp[HH + i + GSTRIDE] + gp[HH + i + 2 * GSTRIDE]
                   + b_hh[HH + i];
        float gh_n = gp[2 * HH + i] + gp[2 * HH + i + GSTRIDE]
                   + gp[2 * HH + i + 2 * GSTRIDE] + b_hh[2 * HH + i];

        float r = 1.0f / (1.0f + expf(-(gi_r + gh_r)));
        float z = 1.0f / (1.0f + expf(-(gi_z + gh_z)));
        float n = tanhf(gi_n + r * gh_n);
        float hn = (1.0f - z) * n + z * g_h[g];
        g_h[g] = hn;
        split_h(hn, g_h_hi + g, g_h_lo + g);
    }
}

// ======================= launch =============================================
extern "C" void kernel_launch(void* const* d_in, const int* in_sizes, int n_in,
                              void* d_out, int out_size)
{
    const float* x     = (const float*)d_in[0];
    const float* emb   = (const float*)d_in[1];
    const float* w_ih  = (const float*)d_in[2];
    const float* w_hh  = (const float*)d_in[3];
    const float* b_ih  = (const float*)d_in[4];
    const float* b_hh  = (const float*)d_in[5];
    const float* cls_w = (const float*)d_in[6];
    const float* cls_b = (const float*)d_in[7];
    float* out = (float*)d_out;

    float* eproj;
    __half *emb_hi, *emb_lo, *wih_hi, *wih_lo;
    cudaGetSymbolAddress((void**)&eproj,  g_eproj);
    cudaGetSymbolAddress((void**)&emb_hi, g_emb_hi);
    cudaGetSymbolAddress((void**)&emb_lo, g_emb_lo);
    cudaGetSymbolAddress((void**)&wih_hi, g_wih_hi);
    cudaGetSymbolAddress((void**)&wih_lo, g_wih_lo);

    cudaFuncSetAttribute(k_gemm_h, cudaFuncAttributeMaxDynamicSharedMemorySize,
                         GEMM_SMEM_B);
    cudaFuncSetAttribute(k_gemm_bal, cudaFuncAttributeMaxDynamicSharedMemorySize,
                         GEMM_SMEM_B);

    // 1: init (h, out[:,0,:], idx, zero partial buffers)
    k_init<<<(BB * VV + 255) / 256, 256>>>(x, out);
    // 2: split all 4 weight matrices to fp16 hi/lo (vectorized x4)
    k_split_all<<<(N_ALL / 4 + 255) / 256, 256>>>(emb, w_ih, w_hh, cls_w);
    // 3: E_proj = emb @ w_ih^T   [V, 3H]  (b_ih added in k_post)
    k_gemm_h<<<(VV / 128) * (H3 / 128), 512, GEMM_SMEM_B>>>(
        emb_hi, emb_lo, wih_hi, wih_lo, eproj, H3, EMB);
    // 4: gh(1) partials (balanced kernel clamped to gh tiles)
    k_gemm_bal<<<NCTA, 512, GEMM_SMEM_B>>>(UGH);
    // 5: gates only -> h(1)
    k_post<<<BB, 1024>>>(out, 0, 0, cls_b, b_ih, b_hh);

    for (int t = 1; t < TT; t++) {
        k_gemm_bal<<<NCTA, 512, GEMM_SMEM_B>>>(UTOT);
        k_post<<<BB, 1024>>>(out, t, 1, cls_b, b_ih, b_hh);
    }
}

// round 17
// speedup vs baseline: 1.1299x; 1.1299x over previous
#include <cuda_runtime.h>
#include <cuda_fp16.h>
#include <math.h>
#include <stdint.h>

#define BB  128
#define EMB 512
#define HH  1024
#define H3  3072
#define VV  8192
#define TT  100

#define LO_SCALE   2048.0f
#define LO_INV     (1.0f / 2048.0f)

#define NSPLIT  3
#define LSTRIDE (BB * VV)
#define GSTRIDE (BB * H3)

#define NCTA    148
#define NTILES  88            // 24 gh + 64 logits
#define UTOT    (NTILES * 32) // 2816 kt-units
#define UGH     (24 * 32)     // 768 gh-only kt-units

// ======================= device scratch (no allocs allowed) ==================
__device__ float g_h[BB * HH];
__device__ int   g_idx[BB];
__device__ float g_eproj[(size_t)VV * H3];
__device__ float g_gh_p[NSPLIT * BB * H3];
__device__ float g_logits_p[NSPLIT * BB * VV];

__device__ __align__(128) __half g_h_hi[BB * HH];
__device__ __align__(128) __half g_h_lo[BB * HH];
__device__ __align__(128) __half g_emb_hi[(size_t)VV * EMB];
__device__ __align__(128) __half g_emb_lo[(size_t)VV * EMB];
__device__ __align__(128) __half g_wih_hi[(size_t)H3 * EMB];
__device__ __align__(128) __half g_wih_lo[(size_t)H3 * EMB];
__device__ __align__(128) __half g_whh_hi[(size_t)H3 * HH];
__device__ __align__(128) __half g_whh_lo[(size_t)H3 * HH];
__device__ __align__(128) __half g_cls_hi[(size_t)VV * HH];
__device__ __align__(128) __half g_cls_lo[(size_t)VV * HH];

// ======================= helpers ============================================
__device__ __forceinline__ uint32_t smem_u32(const void* p) {
    uint32_t a;
    asm("{ .reg .u64 t; cvta.to.shared.u64 t, %1; cvt.u32.u64 %0, t; }"
        : "=r"(a) : "l"(p));
    return a;
}
__device__ __forceinline__ void cpasync16(uint32_t dst, const void* src) {
    asm volatile("cp.async.cg.shared.global [%0], [%1], 16;"
                 :: "r"(dst), "l"(src) : "memory");
}
#define CP_COMMIT() asm volatile("cp.async.commit_group;" ::: "memory")

__device__ __forceinline__ void mma16(float c[4], const uint32_t a[4], const uint32_t b[2]) {
    asm volatile(
        "mma.sync.aligned.m16n8k16.row.col.f32.f16.f16.f32 "
        "{%0,%1,%2,%3}, {%4,%5,%6,%7}, {%8,%9}, {%0,%1,%2,%3};"
        : "+f"(c[0]), "+f"(c[1]), "+f"(c[2]), "+f"(c[3])
        : "r"(a[0]), "r"(a[1]), "r"(a[2]), "r"(a[3]), "r"(b[0]), "r"(b[1]));
}

#define LDSM_X4(r0, r1, r2, r3, addr) \
    asm volatile("ldmatrix.sync.aligned.m8n8.x4.shared.b16 {%0,%1,%2,%3}, [%4];" \
                 : "=r"(r0), "=r"(r1), "=r"(r2), "=r"(r3) : "r"(addr))

#define SROW        40
#define PLANE_H     (128 * SROW)
#define PLANE_B     (PLANE_H * 2)
#define STAGE_H     (4 * PLANE_H)
#define STAGE_B     (4 * PLANE_B)         // 40960
#define NSTAGE      4
#define GEMM_SMEM_B (NSTAGE * STAGE_B)    // 163840

// owner CTA of global kt-unit u under the (UTOT, NCTA) contiguous partition
__device__ __forceinline__ int unit_owner(int u) {
    return (u * NCTA + NCTA - 1) / UTOT;
}

// ======================= balanced step GEMM (512 thr, 4m x 4n warps) =========
// R15 core (proven best: prefetch distance 3, fp32 correction accumulators).
__global__ __launch_bounds__(512, 1)
void k_gemm_bal(int uMax)
{
    extern __shared__ __half smh[];
    const uint32_t sb = smem_u32(smh);

    const int cta  = blockIdx.x;
    const int tid  = threadIdx.x;
    const int wid  = tid >> 5, lane = tid & 31;
    const int grp  = lane >> 2, tig = lane & 3;
    const int wm   = wid & 3, wn = wid >> 2;     // 4 m-warps x 4 n-warps
    const int mo   = wm * 32, no = wn * 32;

    const int rc = tid >> 2, kp = tid & 3;       // gmem->smem chunk coords

    const uint32_t offA = (uint32_t)((mo + (lane & 7) + ((lane >> 3) & 1) * 8) * SROW
                                     + (lane >> 4) * 8) * 2;
    const uint32_t offB = (uint32_t)((no + (lane & 7) + (lane >> 4) * 8) * SROW
                                     + ((lane >> 3) & 1) * 8) * 2;

    int u  = (cta * UTOT) / NCTA;
    int u1 = ((cta + 1) * UTOT) / NCTA;
    if (u1 > uMax) u1 = uMax;

    while (u < u1) {
        const int tile = u >> 5;
        const int ktl0 = u & 31;
        int nkt = 32 - ktl0;
        if (nkt > u1 - u) nkt = u1 - u;
        const int slot = cta - unit_owner(tile << 5);

        // target decode
        const __half *Bhi, *Blo; float* C; int N; int n0;
        if (tile < 24) {
            Bhi = g_whh_hi; Blo = g_whh_lo;
            C = g_gh_p + (size_t)slot * GSTRIDE; N = H3; n0 = tile << 7;
        } else {
            Bhi = g_cls_hi; Blo = g_cls_lo;
            C = g_logits_p + (size_t)slot * LSTRIDE; N = VV; n0 = (tile - 24) << 7;
        }
        const int K = HH;

        const __half* gp[4];
        gp[0] = g_h_hi + (ktl0 << 5);
        gp[1] = g_h_lo + (ktl0 << 5);
        gp[2] = Bhi + (size_t)n0 * K + (ktl0 << 5);
        gp[3] = Blo + (size_t)n0 * K + (ktl0 << 5);

        float cm[2][4][4], cl[2][4][4];
#pragma unroll
        for (int mb = 0; mb < 2; mb++)
#pragma unroll
            for (int j = 0; j < 4; j++)
#pragma unroll
                for (int i = 0; i < 4; i++) { cm[mb][j][i] = 0.0f; cl[mb][j][i] = 0.0f; }

        auto load_stage = [&](int kt, int st) {
            const int koff = kt << 5;
            const uint32_t base = sb + st * STAGE_B;
#pragma unroll
            for (int p = 0; p < 4; p++)
                cpasync16(base + p * PLANE_B + rc * (SROW * 2) + kp * 16,
                          gp[p] + (size_t)rc * K + koff + kp * 8);
            CP_COMMIT();
        };

        __syncthreads();   // prior segment's smem reads done before refill
        load_stage(0, 0);
        if (nkt > 1) load_stage(1, 1);
        if (nkt > 2) load_stage(2, 2);

        for (int kt = 0; kt < nkt; kt++) {
            const int rem = nkt - 1 - kt;
            if (rem >= 2)      asm volatile("cp.async.wait_group 2;" ::: "memory");
            else if (rem == 1) asm volatile("cp.async.wait_group 1;" ::: "memory");
            else               asm volatile("cp.async.wait_group 0;" ::: "memory");
            __syncthreads();
            if (kt + 3 < nkt) load_stage(kt + 3, (kt + 3) & (NSTAGE - 1));

            const uint32_t stb = sb + (kt & (NSTAGE - 1)) * STAGE_B;
            const uint32_t aHi = stb + offA;
            const uint32_t aLo = aHi + PLANE_B;
            const uint32_t bHi = stb + 2 * PLANE_B + offB;
            const uint32_t bLo = bHi + PLANE_B;

#pragma unroll
            for (int ks = 0; ks < 2; ks++) {
                const uint32_t kso = ks * 32;
                uint32_t ah[2][4], al[2][4];
#pragma unroll
                for (int mb = 0; mb < 2; mb++) {
                    const uint32_t amb = mb * (16 * SROW * 2) + kso;
                    LDSM_X4(ah[mb][0], ah[mb][1], ah[mb][2], ah[mb][3], aHi + amb);
                    LDSM_X4(al[mb][0], al[mb][1], al[mb][2], al[mb][3], aLo + amb);
                }
                uint32_t bh[4][2], bl[4][2];
#pragma unroll
                for (int jj = 0; jj < 4; jj += 2) {
                    const uint32_t bj = jj * (8 * SROW * 2) + kso;
                    LDSM_X4(bh[jj][0], bh[jj][1], bh[jj+1][0], bh[jj+1][1], bHi + bj);
                    LDSM_X4(bl[jj][0], bl[jj][1], bl[jj+1][0], bl[jj+1][1], bLo + bj);
                }
#pragma unroll
                for (int j = 0; j < 4; j++)
#pragma unroll
                    for (int mb = 0; mb < 2; mb++)
                        mma16(cm[mb][j], ah[mb], bh[j]);
#pragma unroll
                for (int j = 0; j < 4; j++)
#pragma unroll
                    for (int mb = 0; mb < 2; mb++)
                        mma16(cl[mb][j], ah[mb], bl[j]);
#pragma unroll
                for (int j = 0; j < 4; j++)
#pragma unroll
                    for (int mb = 0; mb < 2; mb++)
                        mma16(cl[mb][j], al[mb], bh[j]);
            }
        }

        // epilogue: C_slot = cm + cl*2^-11
#pragma unroll
        for (int mb = 0; mb < 2; mb++) {
#pragma unroll
            for (int j = 0; j < 4; j++) {
                const int col = n0 + no + j * 8 + 2 * tig;
                const int r0 = mo + mb * 16 + grp;
                const int r1 = r0 + 8;
                float2 v0, v1;
                v0.x = cm[mb][j][0] + cl[mb][j][0] * LO_INV;
                v0.y = cm[mb][j][1] + cl[mb][j][1] * LO_INV;
                v1.x = cm[mb][j][2] + cl[mb][j][2] * LO_INV;
                v1.y = cm[mb][j][3] + cl[mb][j][3] * LO_INV;
                *(float2*)(C + (size_t)r0 * N + col) = v0;
                *(float2*)(C + (size_t)r1 * N + col) = v1;
            }
        }

        u += nkt;
    }
}

// ======================= generic GEMM (eproj prologue only) ==================
__global__ __launch_bounds__(512, 1)
void k_gemm_h(const __half* __restrict__ Ahi, const __half* __restrict__ Alo,
              const __half* __restrict__ Bhi, const __half* __restrict__ Blo,
              float* __restrict__ C, int N, int K)
{
    extern __shared__ __half smh[];
    const uint32_t sb = smem_u32(smh);

    const int tid  = threadIdx.x;
    const int wid  = tid >> 5, lane = tid & 31;
    const int grp  = lane >> 2, tig = lane & 3;
    const int wm   = wid & 3, wn = wid >> 2;
    const int mo   = wm * 32, no = wn * 32;

    const int ntn = N >> 7;
    const int tn = blockIdx.x % ntn, tm = blockIdx.x / ntn;
    const int m0 = tm << 7, n0 = tn << 7;
    const int nk = K >> 5;

    const __half* gp[4];
    gp[0] = Ahi + (size_t)m0 * K;
    gp[1] = Alo + (size_t)m0 * K;
    gp[2] = Bhi + (size_t)n0 * K;
    gp[3] = Blo + (size_t)n0 * K;

    const int rc = tid >> 2, kp = tid & 3;

    const uint32_t offA = (uint32_t)((mo + (lane & 7) + ((lane >> 3) & 1) * 8) * SROW
                                     + (lane >> 4) * 8) * 2;
    const uint32_t offB = (uint32_t)((no + (lane & 7) + (lane >> 4) * 8) * SROW
                                     + ((lane >> 3) & 1) * 8) * 2;

    float cm[2][4][4], cl[2][4][4];
#pragma unroll
    for (int mb = 0; mb < 2; mb++)
#pragma unroll
        for (int j = 0; j < 4; j++)
#pragma unroll
            for (int i = 0; i < 4; i++) { cm[mb][j][i] = 0.0f; cl[mb][j][i] = 0.0f; }

    auto load_stage = [&](int kt, int st) {
        const int koff = kt << 5;
        const uint32_t base = sb + st * STAGE_B;
#pragma unroll
        for (int p = 0; p < 4; p++)
            cpasync16(base + p * PLANE_B + rc * (SROW * 2) + kp * 16,
                      gp[p] + (size_t)rc * K + koff + kp * 8);
        CP_COMMIT();
    };

    load_stage(0, 0);
    load_stage(1, 1);

    for (int kt = 0; kt < nk; kt++) {
        if (kt + 1 < nk) asm volatile("cp.async.wait_group 1;" ::: "memory");
        else             asm volatile("cp.async.wait_group 0;" ::: "memory");
        __syncthreads();
        if (kt + 2 < nk) load_stage(kt + 2, (kt + 2) & (NSTAGE - 1));

        const uint32_t stb = sb + (kt & (NSTAGE - 1)) * STAGE_B;
        const uint32_t aHi = stb + offA;
        const uint32_t aLo = aHi + PLANE_B;
        const uint32_t bHi = stb + 2 * PLANE_B + offB;
        const uint32_t bLo = bHi + PLANE_B;

#pragma unroll
        for (int ks = 0; ks < 2; ks++) {
            const uint32_t kso = ks * 32;
            uint32_t ah[2][4], al[2][4];
#pragma unroll
            for (int mb = 0; mb < 2; mb++) {
                const uint32_t amb = mb * (16 * SROW * 2) + kso;
                LDSM_X4(ah[mb][0], ah[mb][1], ah[mb][2], ah[mb][3], aHi + amb);
                LDSM_X4(al[mb][0], al[mb][1], al[mb][2], al[mb][3], aLo + amb);
            }
            uint32_t bh[4][2], bl[4][2];
#pragma unroll
            for (int jj = 0; jj < 4; jj += 2) {
                const uint32_t bj = jj * (8 * SROW * 2) + kso;
                LDSM_X4(bh[jj][0], bh[jj][1], bh[jj+1][0], bh[jj+1][1], bHi + bj);
                LDSM_X4(bl[jj][0], bl[jj][1], bl[jj+1][0], bl[jj+1][1], bLo + bj);
            }
#pragma unroll
            for (int j = 0; j < 4; j++)
#pragma unroll
                for (int mb = 0; mb < 2; mb++)
                    mma16(cm[mb][j], ah[mb], bh[j]);
#pragma unroll
            for (int j = 0; j < 4; j++)
#pragma unroll
                for (int mb = 0; mb < 2; mb++)
                    mma16(cl[mb][j], ah[mb], bl[j]);
#pragma unroll
            for (int j = 0; j < 4; j++)
#pragma unroll
                for (int mb = 0; mb < 2; mb++)
                    mma16(cl[mb][j], al[mb], bh[j]);
        }
    }

#pragma unroll
    for (int mb = 0; mb < 2; mb++) {
#pragma unroll
        for (int j = 0; j < 4; j++) {
            const int col = n0 + no + j * 8 + 2 * tig;
            const int r0 = m0 + mo + mb * 16 + grp;
            const int r1 = r0 + 8;
            float2 v0, v1;
            v0.x = cm[mb][j][0] + cl[mb][j][0] * LO_INV;
            v0.y = cm[mb][j][1] + cl[mb][j][1] * LO_INV;
            v1.x = cm[mb][j][2] + cl[mb][j][2] * LO_INV;
            v1.y = cm[mb][j][3] + cl[mb][j][3] * LO_INV;
            *(float2*)(C + (size_t)r0 * N + col) = v0;
            *(float2*)(C + (size_t)r1 * N + col) = v1;
        }
    }
}

// ======================= small kernels ======================================
__device__ __forceinline__ void split_h(float a, __half* hi, __half* lo) {
    __half h = __float2half_rn(a);
    float r = a - __half2float(h);
    *hi = h;
    *lo = __float2half_rn(r * LO_SCALE);
}

__device__ __forceinline__ void split4(const float* src, __half* hi, __half* lo,
                                       int j) {
    float4 v = *(const float4*)(src + j);
    __half h0, h1, h2, h3, l0, l1, l2, l3;
    split_h(v.x, &h0, &l0); split_h(v.y, &h1, &l1);
    split_h(v.z, &h2, &l2); split_h(v.w, &h3, &l3);
    *(__half2*)(hi + j)     = __halves2half2(h0, h1);
    *(__half2*)(hi + j + 2) = __halves2half2(h2, h3);
    *(__half2*)(lo + j)     = __halves2half2(l0, l1);
    *(__half2*)(lo + j + 2) = __halves2half2(l2, l3);
}

#define N_EMB (VV * EMB)
#define N_WIH (H3 * EMB)
#define N_WHH (H3 * HH)
#define N_CLS (VV * HH)
#define N_ALL (N_EMB + N_WIH + N_WHH + N_CLS)

__global__ void k_split_all(const float* __restrict__ emb,
                            const float* __restrict__ w_ih,
                            const float* __restrict__ w_hh,
                            const float* __restrict__ cls_w)
{
    int i = (blockIdx.x * blockDim.x + threadIdx.x) * 4;
    if (i >= N_ALL) return;
    if (i < N_EMB) {
        split4(emb, g_emb_hi, g_emb_lo, i);
    } else if (i < N_EMB + N_WIH) {
        split4(w_ih, g_wih_hi, g_wih_lo, i - N_EMB);
    } else if (i < N_EMB + N_WIH + N_WHH) {
        split4(w_hh, g_whh_hi, g_whh_lo, i - N_EMB - N_WIH);
    } else {
        split4(cls_w, g_cls_hi, g_cls_lo, i - N_EMB - N_WIH - N_WHH);
    }
}

__global__ void k_init(const float* __restrict__ x, float* __restrict__ out)
{
    int i = blockIdx.x * blockDim.x + threadIdx.x;      // grid covers BB*VV
    float L = logf(expf(1.0f) + (float)(VV - 1));
    if (i < BB * VV) {
        int b = i / VV, v = i % VV;
        out[(size_t)b * TT * VV + v] = (v == 0 ? 1.0f : 0.0f) - L;
        // zero all partial slots (statically-unwritten ones must read as 0)
#pragma unroll
        for (int j = 0; j < NSPLIT; j++) g_logits_p[i + j * LSTRIDE] = 0.0f;
        if (i < NSPLIT * BB * H3 - BB * VV)
            g_gh_p[BB * VV + i] = 0.0f;
        if (i < BB * VV) {
            if (i < NSPLIT * BB * H3 && i < BB * VV) g_gh_p[i] = 0.0f;
        }
    }
    if (i < BB * HH) {
        float h = x[i];
        g_h[i] = h;
        split_h(h, g_h_hi + i, g_h_lo + i);
    }
    if (i < BB) g_idx[i] = 0;
}

// ======================= fused softmax + argmax + GRU gates ==================
// Warp-shuffle reductions (4 barriers instead of 20); contiguous float4 I/O.
__global__ __launch_bounds__(1024)
void k_post(float* __restrict__ out, int t, int doSoftmax,
            const float* __restrict__ cls_b,
            const float* __restrict__ b_ih,
            const float* __restrict__ b_hh)
{
    const int b = blockIdx.x;
    const int tid = threadIdx.x;
    const int lane = tid & 31, wrp = tid >> 5;

    __shared__ float s_v[96];   // [0..31] warp max, [32..63] warp sum, [64] lse
    __shared__ int   s_i[33];   // [0..31] warp argmax, [32] global argmax

    int gidx;
    if (doSoftmax) {
        const float* lp = g_logits_p + (size_t)b * VV;
        float* orow = out + ((size_t)b * TT + t) * VV;
        const int base = tid * 8;                 // contiguous 8 elems/thread

        float x[8];
        {
            const float4* p0 = (const float4*)(lp + base);
            const float4* p1 = (const float4*)(lp + base + LSTRIDE);
            const float4* p2 = (const float4*)(lp + base + 2 * LSTRIDE);
            const float4* pb = (const float4*)(cls_b + base);
#pragma unroll
            for (int q = 0; q < 2; q++) {
                float4 a = p0[q], c = p1[q], d = p2[q], e = pb[q];
                x[q * 4 + 0] = a.x + c.x + d.x + e.x;
                x[q * 4 + 1] = a.y + c.y + d.y + e.y;
                x[q * 4 + 2] = a.z + c.z + d.z + e.z;
                x[q * 4 + 3] = a.w + c.w + d.w + e.w;
            }
        }

        float mx = x[0]; int ai = base;
#pragma unroll
        for (int j = 1; j < 8; j++)
            if (x[j] > mx) { mx = x[j]; ai = base + j; }

        // warp argmax reduce (lower index wins ties)
#pragma unroll
        for (int o = 16; o > 0; o >>= 1) {
            float v2 = __shfl_xor_sync(0xFFFFFFFFu, mx, o);
            int   i2 = __shfl_xor_sync(0xFFFFFFFFu, ai, o);
            if (v2 > mx || (v2 == mx && i2 < ai)) { mx = v2; ai = i2; }
        }
        if (lane == 0) { s_v[wrp] = mx; s_i[wrp] = ai; }
        __syncthreads();
        if (wrp == 0) {
            float m2 = s_v[lane]; int a2 = s_i[lane];
#pragma unroll
            for (int o = 16; o > 0; o >>= 1) {
                float v2 = __shfl_xor_sync(0xFFFFFFFFu, m2, o);
                int   i2 = __shfl_xor_sync(0xFFFFFFFFu, a2, o);
                if (v2 > m2 || (v2 == m2 && i2 < a2)) { m2 = v2; a2 = i2; }
            }
            if (lane == 0) { s_v[64] = m2; s_i[32] = a2; }
        }
        __syncthreads();
        const float gmax = s_v[64];
        gidx = s_i[32];

        float sum = 0.0f;
#pragma unroll
        for (int j = 0; j < 8; j++) sum += __expf(x[j] - gmax);
#pragma unroll
        for (int o = 16; o > 0; o >>= 1)
            sum += __shfl_xor_sync(0xFFFFFFFFu, sum, o);
        if (lane == 0) s_v[32 + wrp] = sum;
        __syncthreads();
        if (wrp == 0) {
            float s2 = s_v[32 + lane];
#pragma unroll
            for (int o = 16; o > 0; o >>= 1)
                s2 += __shfl_xor_sync(0xFFFFFFFFu, s2, o);
            if (lane == 0) s_v[65] = gmax + logf(s2);
        }
        __syncthreads();
        const float lse = s_v[65];

        {
            float4* po = (float4*)(orow + base);
#pragma unroll
            for (int q = 0; q < 2; q++) {
                float4 o4;
                o4.x = x[q * 4 + 0] - lse;
                o4.y = x[q * 4 + 1] - lse;
                o4.z = x[q * 4 + 2] - lse;
                o4.w = x[q * 4 + 3] - lse;
                po[q] = o4;
            }
        }

        if (tid == 0) g_idx[b] = gidx;
    } else {
        gidx = g_idx[b];
    }

    // ---- GRU gates for h[b, tid] ----
    {
        const int i = tid;
        const int g = b * HH + i;
        const float* ep = g_eproj + (size_t)gidx * H3;
        const float* gp = g_gh_p + (size_t)b * H3;

        float gi_r = ep[i]          + b_ih[i];
        float gi_z = ep[HH + i]     + b_ih[HH + i];
        float gi_n = ep[2 * HH + i] + b_ih[2 * HH + i];

        float gh_r = gp[i] + gp[i + GSTRIDE] + gp[i + 2 * GSTRIDE] + b_hh[i];
        float gh_z = gp[HH + i] + gp[HH + i + GSTRIDE] + gp[HH + i + 2 * GSTRIDE]
                   + b_hh[HH + i];
        float gh_n = gp[2 * HH + i] + gp[2 * HH + i + GSTRIDE]
                   + gp[2 * HH + i + 2 * GSTRIDE] + b_hh[2 * HH + i];

        float r = 1.0f / (1.0f + expf(-(gi_r + gh_r)));
        float z = 1.0f / (1.0f + expf(-(gi_z + gh_z)));
        float n = tanhf(gi_n + r * gh_n);
        float hn = (1.0f - z) * n + z * g_h[g];
        g_h[g] = hn;
        split_h(hn, g_h_hi + g, g_h_lo + g);
    }
}

// ======================= launch =============================================
extern "C" void kernel_launch(void* const* d_in, const int* in_sizes, int n_in,
                              void* d_out, int out_size)
{
    const float* x     = (const float*)d_in[0];
    const float* emb   = (const float*)d_in[1];
    const float* w_ih  = (const float*)d_in[2];
    const float* w_hh  = (const float*)d_in[3];
    const float* b_ih  = (const float*)d_in[4];
    const float* b_hh  = (const float*)d_in[5];
    const float* cls_w = (const float*)d_in[6];
    const float* cls_b = (const float*)d_in[7];
    float* out = (float*)d_out;

    float* eproj;
    __half *emb_hi, *emb_lo, *wih_hi, *wih_lo;
    cudaGetSymbolAddress((void**)&eproj,  g_eproj);
    cudaGetSymbolAddress((void**)&emb_hi, g_emb_hi);
    cudaGetSymbolAddress((void**)&emb_lo, g_emb_lo);
    cudaGetSymbolAddress((void**)&wih_hi, g_wih_hi);
    cudaGetSymbolAddress((void**)&wih_lo, g_wih_lo);

    cudaFuncSetAttribute(k_gemm_h, cudaFuncAttributeMaxDynamicSharedMemorySize,
                         GEMM_SMEM_B);
    cudaFuncSetAttribute(k_gemm_bal, cudaFuncAttributeMaxDynamicSharedMemorySize,
                         GEMM_SMEM_B);

    // 1: init (h, out[:,0,:], idx, zero partial buffers)
    k_init<<<(BB * VV + 255) / 256, 256>>>(x, out);
    // 2: split all 4 weight matrices to fp16 hi/lo (vectorized x4)
    k_split_all<<<(N_ALL / 4 + 255) / 256, 256>>>(emb, w_ih, w_hh, cls_w);
    // 3: E_proj = emb @ w_ih^T   [V, 3H]  (b_ih added in k_post)
    k_gemm_h<<<(VV / 128) * (H3 / 128), 512, GEMM_SMEM_B>>>(
        emb_hi, emb_lo, wih_hi, wih_lo, eproj, H3, EMB);
    // 4: gh(1) partials (balanced kernel clamped to gh tiles)
    k_gemm_bal<<<NCTA, 512, GEMM_SMEM_B>>>(UGH);
    // 5: gates only -> h(1)
    k_post<<<BB, 1024>>>(out, 0, 0, cls_b, b_ih, b_hh);

    for (int t = 1; t < TT; t++) {
        k_gemm_bal<<<NCTA, 512, GEMM_SMEM_B>>>(UTOT);
        k_post<<<BB, 1024>>>(out, t, 1, cls_b, b_ih, b_hh);
    }
}